// round 4
// baseline (speedup 1.0000x reference)
#include <cuda_runtime.h>

// Problem dims (fixed by the reference)
#define Gn   32
#define NN   4000
#define EE   32000
#define FD0  64
#define HD   128
#define BNR  16000
#define STEPS 8
#define LROWS 64        // LSTM rows per block

typedef unsigned long long u64;

__device__ __forceinline__ u64 fma2(u64 a, u64 b, u64 c) {
    u64 d;
    asm("fma.rn.f32x2 %0, %1, %2, %3;" : "=l"(d) : "l"(a), "l"(b), "l"(c));
    return d;
}
__device__ __forceinline__ u64 pack2(float x) {
    u64 d; asm("mov.b64 %0, {%1, %1};" : "=l"(d) : "f"(x)); return d;
}

// ---------------- scratch (device globals) --------------------------------------
__device__ float d_deg_out[Gn * NN];
__device__ float d_deg_in [Gn * NN];
__device__ int   d_cnt_f[Gn * NN];
__device__ int   d_cnt_b[Gn * NN];
__device__ int   d_off_f[Gn * NN];
__device__ int   d_off_b[Gn * NN];
__device__ int   d_cur_f[Gn * NN];
__device__ int   d_cur_b[Gn * NN];
__device__ int   d_csr_if[Gn * EE];
__device__ float d_csr_wf[Gn * EE];
__device__ int   d_csr_ib[Gn * EE];
__device__ float d_csr_wb[Gn * EE];
__device__ float d_aggf  [(size_t)Gn * NN * HD];
__device__ float d_aggb  [(size_t)Gn * NN * HD];
__device__ float d_h0    [(size_t)Gn * NN * HD];
__device__ float d_h1    [(size_t)Gn * NN * HD];
__device__ float d_wT    [256 * 512];   // [k][j]: k<128 -> Wih^T, k>=128 -> Whh^T
__device__ float d_bias  [512];         // bih + bhh
__device__ float d_wpT   [128 * 64];    // Wp^T

// ---------------- CSR build ------------------------------------------------------
__global__ void zero_kernel() {
    int i = blockIdx.x * blockDim.x + threadIdx.x;
    if (i < Gn * NN) {
        d_deg_out[i] = 0.f; d_deg_in[i] = 0.f;
        d_cnt_f[i] = 0;     d_cnt_b[i] = 0;
    }
}

__global__ void degcnt_kernel(const int* __restrict__ ei, const float* __restrict__ ew) {
    int i = blockIdx.x * blockDim.x + threadIdx.x;
    if (i >= Gn * EE) return;
    int g = i / EE, e = i - g * EE;
    const int* eig = ei + (size_t)g * 2 * EE;
    int src = eig[e], dst = eig[EE + e];
    float w = ew[i];
    atomicAdd(&d_deg_out[g * NN + src], w);
    atomicAdd(&d_deg_in [g * NN + dst], w);
    atomicAdd(&d_cnt_f[g * NN + dst], 1);
    atomicAdd(&d_cnt_b[g * NN + src], 1);
}

__global__ void inv_kernel() {
    int i = blockIdx.x * blockDim.x + threadIdx.x;
    if (i >= Gn * NN) return;
    float v = d_deg_out[i];
    d_deg_out[i] = (v > 0.f) ? rsqrtf(fmaxf(v, 1e-12f)) : 0.f;
    v = d_deg_in[i];
    d_deg_in[i]  = (v > 0.f) ? rsqrtf(fmaxf(v, 1e-12f)) : 0.f;
}

__global__ void __launch_bounds__(1024) scan_kernel() {
    int g   = blockIdx.x;
    int dir = blockIdx.y;
    const int* cnt = dir ? d_cnt_b : d_cnt_f;
    int* off = dir ? d_off_b : d_off_f;
    int* cur = dir ? d_cur_b : d_cur_f;
    int tid = threadIdx.x;
    int base = g * NN;
    int v[4], tot = 0;
#pragma unroll
    for (int k = 0; k < 4; k++) {
        int i = tid * 4 + k;
        v[k] = (i < NN) ? cnt[base + i] : 0;
        tot += v[k];
    }
    __shared__ int s[1024];
    s[tid] = tot;
    __syncthreads();
    for (int d = 1; d < 1024; d <<= 1) {
        int t = (tid >= d) ? s[tid - d] : 0;
        __syncthreads();
        s[tid] += t;
        __syncthreads();
    }
    int ex = s[tid] - tot;
#pragma unroll
    for (int k = 0; k < 4; k++) {
        int i = tid * 4 + k;
        if (i < NN) { off[base + i] = ex; cur[base + i] = ex; ex += v[k]; }
    }
}

__global__ void scatter_kernel(const int* __restrict__ ei, const float* __restrict__ ew) {
    int i = blockIdx.x * blockDim.x + threadIdx.x;
    if (i >= Gn * EE) return;
    int g = i / EE, e = i - g * EE;
    const int* eig = ei + (size_t)g * 2 * EE;
    int src = eig[e], dst = eig[EE + e];
    float w = ew[i] * d_deg_out[g * NN + src] * d_deg_in[g * NN + dst];
    int pf = atomicAdd(&d_cur_f[g * NN + dst], 1);
    d_csr_if[g * EE + pf] = src;
    d_csr_wf[g * EE + pf] = w;
    int pb = atomicAdd(&d_cur_b[g * NN + src], 1);
    d_csr_ib[g * EE + pb] = dst;
    d_csr_wb[g * EE + pb] = w;
}

// ---------------- gather aggregation: one warp per (node, dir) -------------------
template<int FD>
__global__ void __launch_bounds__(256) gather_kernel(const float* __restrict__ x) {
    int gw = (blockIdx.x * 256 + threadIdx.x) >> 5;
    int lane = threadIdx.x & 31;
    if (gw >= Gn * NN * 2) return;
    int dir = gw & 1;
    int gn  = gw >> 1;
    int g   = gn / NN;
    const int*   off = dir ? d_off_b : d_off_f;
    const int*   cnt = dir ? d_cnt_b : d_cnt_f;
    const int*   nb  = dir ? d_csr_ib : d_csr_if;
    const float* wv  = dir ? d_csr_wb : d_csr_wf;
    float* outp      = dir ? d_aggb   : d_aggf;
    int o = off[gn], c = cnt[gn];
    const float* xg = x + (size_t)g * NN * FD;
    const int ebase = g * EE + o;

    if (FD == 128) {
        float4 acc = make_float4(0.f, 0.f, 0.f, 0.f);
        for (int j = 0; j < c; j++) {
            int   s = nb[ebase + j];
            float w = wv[ebase + j];
            float4 xv = *(const float4*)(xg + (size_t)s * FD + lane * 4);
            acc.x += w * xv.x; acc.y += w * xv.y;
            acc.z += w * xv.z; acc.w += w * xv.w;
        }
        *(float4*)(outp + (size_t)gn * FD + lane * 4) = acc;
    } else {
        float2 acc = make_float2(0.f, 0.f);
        for (int j = 0; j < c; j++) {
            int   s = nb[ebase + j];
            float w = wv[ebase + j];
            float2 xv = *(const float2*)(xg + (size_t)s * FD + lane * 2);
            acc.x += w * xv.x; acc.y += w * xv.y;
        }
        *(float2*)(outp + (size_t)gn * FD + lane * 2) = acc;
    }
}

// ---------------- FMA2 GEMM: 128x128 block tile, 8x8/thread ---------------------
// Thread (ty,tx) owns rows ty*8..+7 and cols {tx*4..+3, 64+tx*4..+3} (conflict-free).
template<int KD, bool DUAL>
__global__ void __launch_bounds__(256)
gemm2_kernel(const float* __restrict__ A0, const float* __restrict__ A1,
             const float* __restrict__ W0, const float* __restrict__ W1,
             const float* __restrict__ b0, const float* __restrict__ b1,
             float* __restrict__ C, int M, int NC,
             float s0, float s1, float bs0, float bs1)
{
    __shared__ float As[16][132];
    __shared__ float Ws[16][132];
    const int tid = threadIdx.x;
    const int m0  = blockIdx.x * 128;
    const int jn  = blockIdx.y * 128;
    const int ty  = tid >> 4;
    const int tx  = tid & 15;

    u64 acc[8][4];
#pragma unroll
    for (int r = 0; r < 8; r++)
#pragma unroll
        for (int cidx = 0; cidx < 4; cidx++) acc[r][cidx] = 0ull;

    const int npass = DUAL ? 2 : 1;
    for (int pass = 0; pass < npass; pass++) {
        const float* A = pass ? A1 : A0;
        const float* W = pass ? W1 : W0;
        const float  s = pass ? s1 : s0;
        for (int kt = 0; kt < KD; kt += 16) {
            __syncthreads();
#pragma unroll
            for (int half = 0; half < 2; half++) {
                int r  = (tid >> 2) + half * 64;
                int k4 = (tid & 3) << 2;
                float4 v = *(const float4*)(A + (size_t)(m0 + r) * KD + kt + k4);
                As[k4 + 0][r] = v.x; As[k4 + 1][r] = v.y;
                As[k4 + 2][r] = v.z; As[k4 + 3][r] = v.w;
            }
#pragma unroll
            for (int half = 0; half < 2; half++) {
                int j  = (tid >> 2) + half * 64;
                int k4 = (tid & 3) << 2;
                float4 v = *(const float4*)(W + (size_t)(jn + j) * KD + kt + k4);
                Ws[k4 + 0][j] = v.x * s; Ws[k4 + 1][j] = v.y * s;
                Ws[k4 + 2][j] = v.z * s; Ws[k4 + 3][j] = v.w * s;
            }
            __syncthreads();
#pragma unroll
            for (int kk = 0; kk < 16; kk++) {
                float a[8];
                *(float4*)&a[0] = *(const float4*)&As[kk][ty * 8];
                *(float4*)&a[4] = *(const float4*)&As[kk][ty * 8 + 4];
                float4 wA = *(const float4*)&Ws[kk][tx * 4];
                float4 wB = *(const float4*)&Ws[kk][64 + tx * 4];
                u64 w01 = *(const u64*)&wA.x;
                u64 w23 = *(const u64*)&wA.z;
                u64 w45 = *(const u64*)&wB.x;
                u64 w67 = *(const u64*)&wB.z;
#pragma unroll
                for (int r = 0; r < 8; r++) {
                    u64 aa = pack2(a[r]);
                    acc[r][0] = fma2(aa, w01, acc[r][0]);
                    acc[r][1] = fma2(aa, w23, acc[r][1]);
                    acc[r][2] = fma2(aa, w45, acc[r][2]);
                    acc[r][3] = fma2(aa, w67, acc[r][3]);
                }
            }
        }
    }

    int j1 = jn + tx * 4;
    int j2 = jn + 64 + tx * 4;
    float biasA[4], biasB[4];
#pragma unroll
    for (int cidx = 0; cidx < 4; cidx++) {
        biasA[cidx] = bs0 * b0[j1 + cidx] + bs1 * b1[j1 + cidx];
        biasB[cidx] = bs0 * b0[j2 + cidx] + bs1 * b1[j2 + cidx];
    }
#pragma unroll
    for (int r = 0; r < 8; r++) {
        int m = m0 + ty * 8 + r;
        float2 p0 = *(float2*)&acc[r][0];
        float2 p1 = *(float2*)&acc[r][1];
        float2 p2 = *(float2*)&acc[r][2];
        float2 p3 = *(float2*)&acc[r][3];
        float4 o0 = make_float4(p0.x + biasA[0], p0.y + biasA[1], p1.x + biasA[2], p1.y + biasA[3]);
        float4 o1 = make_float4(p2.x + biasB[0], p2.y + biasB[1], p3.x + biasB[2], p3.y + biasB[3]);
        *(float4*)(C + (size_t)m * NC + j1) = o0;
        *(float4*)(C + (size_t)m * NC + j2) = o1;
    }
}

// ---------------- prep: build [Wih;Whh]^T, bias sum, Wp^T -----------------------
__global__ void prep_kernel(const float* __restrict__ Wih, const float* __restrict__ Whh,
                            const float* __restrict__ bih, const float* __restrict__ bhh,
                            const float* __restrict__ Wp) {
    int i = blockIdx.x * blockDim.x + threadIdx.x;
    if (i < 512 * 128) {
        int j = i >> 7, k = i & 127;
        d_wT[(size_t)k * 512 + j]         = Wih[i];
        d_wT[(size_t)(128 + k) * 512 + j] = Whh[i];
    }
    if (i < 512) d_bias[i] = bih[i] + bhh[i];
    if (i < 64 * 128) {
        int j = i >> 7, k = i & 127;
        d_wpT[k * 64 + j] = Wp[i];
    }
}

// ---------------- fused LSTM: input GEMM + recurrence + projection --------------
__device__ __forceinline__ float sigmoidf_(float x) { return 1.f / (1.f + __expf(-x)); }

__global__ void __launch_bounds__(512)
lstm_fused_kernel(const float* __restrict__ h1, float* __restrict__ out,
                  const float* __restrict__ bp)
{
    __shared__ float x_s[LROWS][132];
    __shared__ float h_s[LROWS][132];
    __shared__ float w_s[16][512];     // also reused for Wp^T [128][64] in epilogue
    const int tid  = threadIdx.x;
    const int tc   = tid & 31;
    const int tr   = tid >> 5;         // 0..15 -> rows tr*4..tr*4+3
    const int row0 = blockIdx.x * LROWS;

    // bias preload: gates at cols gate*128 + tc*4
    u64 bias[4][2];
#pragma unroll
    for (int g = 0; g < 4; g++) {
        float4 bv = *(const float4*)(d_bias + g * 128 + tc * 4);
        bias[g][0] = *(const u64*)&bv.x;
        bias[g][1] = *(const u64*)&bv.z;
    }

    float c[4][4];
#pragma unroll
    for (int a = 0; a < 4; a++)
#pragma unroll
        for (int b = 0; b < 4; b++) c[a][b] = 0.f;

    for (int t = 0; t < STEPS; t++) {
        // stage x_s: rows (row0+i)*8+t of h1, i = 0..63
        {
            int xi = tid >> 3;
            const float* src = h1 + ((size_t)(row0 + xi) * STEPS + t) * 128;
#pragma unroll
            for (int jj = 0; jj < 4; jj++) {
                int ch = (tid & 7) + jj * 8;      // float4 chunk 0..31
                *(float4*)&x_s[xi][ch * 4] = *(const float4*)(src + ch * 4);
            }
        }

        u64 acc[4][4][2];
#pragma unroll
        for (int g = 0; g < 4; g++)
#pragma unroll
            for (int ri = 0; ri < 4; ri++) {
                acc[g][ri][0] = bias[g][0];
                acc[g][ri][1] = bias[g][1];
            }

        const int ktmax = (t > 0) ? 16 : 8;   // k<128: input part; k>=128: recurrent
        for (int kt = 0; kt < ktmax; kt++) {
            __syncthreads();
#pragma unroll
            for (int i = 0; i < 4; i++) {     // stage w_s[16][512] tile
                int q  = tid + i * 512;
                int kk = q >> 7;
                int j4 = (q & 127) << 2;
                *(float4*)&w_s[kk][j4] =
                    *(const float4*)(d_wT + (size_t)(kt * 16 + kk) * 512 + j4);
            }
            __syncthreads();
            const bool useh = (kt >= 8);
            const int  kb   = useh ? (kt - 8) * 16 : kt * 16;
#pragma unroll
            for (int kk = 0; kk < 16; kk++) {
                u64 hp[4];
#pragma unroll
                for (int ri = 0; ri < 4; ri++) {
                    float v = useh ? h_s[tr * 4 + ri][kb + kk]
                                   : x_s[tr * 4 + ri][kb + kk];
                    hp[ri] = pack2(v);
                }
#pragma unroll
                for (int g = 0; g < 4; g++) {
                    float4 w = *(const float4*)&w_s[kk][g * 128 + tc * 4];
                    u64 w01 = *(const u64*)&w.x;
                    u64 w23 = *(const u64*)&w.z;
#pragma unroll
                    for (int ri = 0; ri < 4; ri++) {
                        acc[g][ri][0] = fma2(hp[ri], w01, acc[g][ri][0]);
                        acc[g][ri][1] = fma2(hp[ri], w23, acc[g][ri][1]);
                    }
                }
            }
        }

        // gates -> h, c (each warp touches only its own 4 rows of h_s)
#pragma unroll
        for (int ri = 0; ri < 4; ri++) {
            float2 i01 = *(float2*)&acc[0][ri][0], i23 = *(float2*)&acc[0][ri][1];
            float2 f01 = *(float2*)&acc[1][ri][0], f23 = *(float2*)&acc[1][ri][1];
            float2 g01 = *(float2*)&acc[2][ri][0], g23 = *(float2*)&acc[2][ri][1];
            float2 o01 = *(float2*)&acc[3][ri][0], o23 = *(float2*)&acc[3][ri][1];
            float ig[4] = {i01.x, i01.y, i23.x, i23.y};
            float fg[4] = {f01.x, f01.y, f23.x, f23.y};
            float gg[4] = {g01.x, g01.y, g23.x, g23.y};
            float og[4] = {o01.x, o01.y, o23.x, o23.y};
            float hn[4];
#pragma unroll
            for (int ci = 0; ci < 4; ci++) {
                float iv = sigmoidf_(ig[ci]);
                float fv = sigmoidf_(fg[ci]);
                float gv = tanhf(gg[ci]);
                float ov = sigmoidf_(og[ci]);
                float cn = fv * c[ri][ci] + iv * gv;
                c[ri][ci] = cn;
                hn[ci] = ov * tanhf(cn);
            }
            *(float4*)&h_s[tr * 4 + ri][tc * 4] = make_float4(hn[0], hn[1], hn[2], hn[3]);
        }
        __syncthreads();   // x_s restage + cross-warp h_s use next phase
    }

    // ---- projection: out[row0+prow][0..63] = h_s[prow] @ Wp^T + bp ----
    float* wp = &w_s[0][0];   // reuse as [128][64]
#pragma unroll
    for (int i = 0; i < 4; i++) {
        int q = tid + i * 512;             // 2048 float4 chunks
        *(float4*)&wp[q * 4] = *(const float4*)(d_wpT + q * 4);
    }
    __syncthreads();

    const int prow = tid >> 3;             // 0..63
    const int cg   = tid & 7;              // cols cg*8..+7
    u64 pacc[4] = {0ull, 0ull, 0ull, 0ull};
#pragma unroll 8
    for (int k = 0; k < 128; k++) {
        u64 hv = pack2(h_s[prow][k]);
        float4 wa = *(const float4*)&wp[k * 64 + cg * 8];
        float4 wb = *(const float4*)&wp[k * 64 + cg * 8 + 4];
        pacc[0] = fma2(hv, *(const u64*)&wa.x, pacc[0]);
        pacc[1] = fma2(hv, *(const u64*)&wa.z, pacc[1]);
        pacc[2] = fma2(hv, *(const u64*)&wb.x, pacc[2]);
        pacc[3] = fma2(hv, *(const u64*)&wb.z, pacc[3]);
    }
    float4 bpa = *(const float4*)(bp + cg * 8);
    float4 bpb = *(const float4*)(bp + cg * 8 + 4);
    float2 q0 = *(float2*)&pacc[0];
    float2 q1 = *(float2*)&pacc[1];
    float2 q2 = *(float2*)&pacc[2];
    float2 q3 = *(float2*)&pacc[3];
    float4 o0 = make_float4(q0.x + bpa.x, q0.y + bpa.y, q1.x + bpa.z, q1.y + bpa.w);
    float4 o1 = make_float4(q2.x + bpb.x, q2.y + bpb.y, q3.x + bpb.z, q3.y + bpb.w);
    *(float4*)(out + (size_t)(row0 + prow) * 64 + cg * 8)     = o0;
    *(float4*)(out + (size_t)(row0 + prow) * 64 + cg * 8 + 4) = o1;
}

// ---------------- launch --------------------------------------------------------
extern "C" void kernel_launch(void* const* d_in, const int* in_sizes, int n_in,
                              void* d_out, int out_size)
{
    const float* x_seq = (const float*)d_in[0];
    const int*   ei    = (const int*)  d_in[1];
    const float* ew    = (const float*)d_in[2];
    const float* W0s   = (const float*)d_in[3];
    const float* b0s   = (const float*)d_in[4];
    const float* W0d   = (const float*)d_in[5];
    const float* b0d   = (const float*)d_in[6];
    const float* W1s   = (const float*)d_in[7];
    const float* b1s   = (const float*)d_in[8];
    const float* W1d   = (const float*)d_in[9];
    const float* b1d   = (const float*)d_in[10];
    const float* Wih   = (const float*)d_in[11];
    const float* Whh   = (const float*)d_in[12];
    const float* bih   = (const float*)d_in[13];
    const float* bhh   = (const float*)d_in[14];
    const float* Wp    = (const float*)d_in[15];
    const float* bp    = (const float*)d_in[16];
    float* out = (float*)d_out;

    float *aggf, *aggb, *h0, *h1;
    cudaGetSymbolAddress((void**)&aggf, d_aggf);
    cudaGetSymbolAddress((void**)&aggb, d_aggb);
    cudaGetSymbolAddress((void**)&h0,   d_h0);
    cudaGetSymbolAddress((void**)&h1,   d_h1);

    const int M = Gn * NN;   // 128000

    // ---- CSR build ----
    zero_kernel<<<(Gn * NN + 255) / 256, 256>>>();
    degcnt_kernel<<<(Gn * EE + 255) / 256, 256>>>(ei, ew);
    inv_kernel<<<(Gn * NN + 255) / 256, 256>>>();
    scan_kernel<<<dim3(Gn, 2), 1024>>>();
    scatter_kernel<<<(Gn * EE + 255) / 256, 256>>>(ei, ew);

    const int gblocks = (Gn * NN * 2 * 32 + 255) / 256;

    // ---- GCN layer 0 (F=64 -> H=128) ----
    gather_kernel<64><<<gblocks, 256>>>(x_seq);
    gemm2_kernel<64, true><<<dim3(M / 128, 1), 256>>>(
        aggf, aggb, W0s, W0d, b0s, b0d, h0, M, HD, 0.5f, 0.5f, 0.5f, 0.5f);

    // ---- GCN layer 1 (H=128 -> H=128) ----
    gather_kernel<128><<<gblocks, 256>>>(h0);
    gemm2_kernel<128, true><<<dim3(M / 128, 1), 256>>>(
        aggf, aggb, W1s, W1d, b1s, b1d, h1, M, HD, 0.5f, 0.5f, 0.5f, 0.5f);

    // ---- fused LSTM (input GEMM + recurrence + projection) ----
    prep_kernel<<<256, 256>>>(Wih, Whh, bih, bhh, Wp);
    lstm_fused_kernel<<<BNR / LROWS, 512>>>(h1, out, bp);
}

// round 5
// speedup vs baseline: 1.5846x; 1.5846x over previous
#include <cuda_runtime.h>

// Problem dims (fixed by the reference)
#define Gn   32
#define NN   4000
#define EE   32000
#define FD0  64
#define HD   128
#define BNR  16000
#define STEPS 8

typedef unsigned long long u64;

__device__ __forceinline__ u64 fma2(u64 a, u64 b, u64 c) {
    u64 d;
    asm("fma.rn.f32x2 %0, %1, %2, %3;" : "=l"(d) : "l"(a), "l"(b), "l"(c));
    return d;
}
__device__ __forceinline__ u64 pack2(float x) {
    u64 d; asm("mov.b64 %0, {%1, %1};" : "=l"(d) : "f"(x)); return d;
}

// ---------------- scratch (device globals) --------------------------------------
__device__ float d_deg_out[Gn * NN];
__device__ float d_deg_in [Gn * NN];
__device__ int   d_cnt_f[Gn * NN];
__device__ int   d_cnt_b[Gn * NN];
__device__ int   d_off_f[Gn * NN];
__device__ int   d_off_b[Gn * NN];
__device__ int   d_cur_f[Gn * NN];
__device__ int   d_cur_b[Gn * NN];
__device__ int   d_csr_if[Gn * EE];
__device__ float d_csr_wf[Gn * EE];
__device__ int   d_csr_ib[Gn * EE];
__device__ float d_csr_wb[Gn * EE];
__device__ float d_aggf  [(size_t)Gn * NN * HD];
__device__ float d_aggb  [(size_t)Gn * NN * HD];
__device__ float d_h0    [(size_t)Gn * NN * HD];
__device__ float d_h1    [(size_t)Gn * NN * HD];
__device__ float d_gx    [(size_t)BNR * STEPS * 4 * HD];
__device__ float d_whhT  [HD * 4 * HD];   // Whh^T [128][512]
__device__ float d_wpT   [HD * FD0];      // Wp^T  [128][64]

// ---------------- CSR build ------------------------------------------------------
__global__ void zero_kernel() {
    int i = blockIdx.x * blockDim.x + threadIdx.x;
    if (i < Gn * NN) {
        d_deg_out[i] = 0.f; d_deg_in[i] = 0.f;
        d_cnt_f[i] = 0;     d_cnt_b[i] = 0;
    }
}

__global__ void degcnt_kernel(const int* __restrict__ ei, const float* __restrict__ ew) {
    int i = blockIdx.x * blockDim.x + threadIdx.x;
    if (i >= Gn * EE) return;
    int g = i / EE, e = i - g * EE;
    const int* eig = ei + (size_t)g * 2 * EE;
    int src = eig[e], dst = eig[EE + e];
    float w = ew[i];
    atomicAdd(&d_deg_out[g * NN + src], w);
    atomicAdd(&d_deg_in [g * NN + dst], w);
    atomicAdd(&d_cnt_f[g * NN + dst], 1);
    atomicAdd(&d_cnt_b[g * NN + src], 1);
}

__global__ void inv_kernel() {
    int i = blockIdx.x * blockDim.x + threadIdx.x;
    if (i >= Gn * NN) return;
    float v = d_deg_out[i];
    d_deg_out[i] = (v > 0.f) ? rsqrtf(fmaxf(v, 1e-12f)) : 0.f;
    v = d_deg_in[i];
    d_deg_in[i]  = (v > 0.f) ? rsqrtf(fmaxf(v, 1e-12f)) : 0.f;
}

__global__ void __launch_bounds__(1024) scan_kernel() {
    int g   = blockIdx.x;
    int dir = blockIdx.y;
    const int* cnt = dir ? d_cnt_b : d_cnt_f;
    int* off = dir ? d_off_b : d_off_f;
    int* cur = dir ? d_cur_b : d_cur_f;
    int tid = threadIdx.x;
    int base = g * NN;
    int v[4], tot = 0;
#pragma unroll
    for (int k = 0; k < 4; k++) {
        int i = tid * 4 + k;
        v[k] = (i < NN) ? cnt[base + i] : 0;
        tot += v[k];
    }
    __shared__ int s[1024];
    s[tid] = tot;
    __syncthreads();
    for (int d = 1; d < 1024; d <<= 1) {
        int t = (tid >= d) ? s[tid - d] : 0;
        __syncthreads();
        s[tid] += t;
        __syncthreads();
    }
    int ex = s[tid] - tot;
#pragma unroll
    for (int k = 0; k < 4; k++) {
        int i = tid * 4 + k;
        if (i < NN) { off[base + i] = ex; cur[base + i] = ex; ex += v[k]; }
    }
}

__global__ void scatter_kernel(const int* __restrict__ ei, const float* __restrict__ ew) {
    int i = blockIdx.x * blockDim.x + threadIdx.x;
    if (i >= Gn * EE) return;
    int g = i / EE, e = i - g * EE;
    const int* eig = ei + (size_t)g * 2 * EE;
    int src = eig[e], dst = eig[EE + e];
    float w = ew[i] * d_deg_out[g * NN + src] * d_deg_in[g * NN + dst];
    int pf = atomicAdd(&d_cur_f[g * NN + dst], 1);
    d_csr_if[g * EE + pf] = src;
    d_csr_wf[g * EE + pf] = w;
    int pb = atomicAdd(&d_cur_b[g * NN + src], 1);
    d_csr_ib[g * EE + pb] = dst;
    d_csr_wb[g * EE + pb] = w;
}

// ---------------- gather aggregation: one warp per (node, dir) -------------------
template<int FD>
__global__ void __launch_bounds__(256) gather_kernel(const float* __restrict__ x) {
    int gw = (blockIdx.x * 256 + threadIdx.x) >> 5;
    int lane = threadIdx.x & 31;
    if (gw >= Gn * NN * 2) return;
    int dir = gw & 1;
    int gn  = gw >> 1;
    int g   = gn / NN;
    const int*   off = dir ? d_off_b : d_off_f;
    const int*   cnt = dir ? d_cnt_b : d_cnt_f;
    const int*   nb  = dir ? d_csr_ib : d_csr_if;
    const float* wv  = dir ? d_csr_wb : d_csr_wf;
    float* outp      = dir ? d_aggb   : d_aggf;
    int o = off[gn], c = cnt[gn];
    const float* xg = x + (size_t)g * NN * FD;
    const int ebase = g * EE + o;

    if (FD == 128) {
        float4 acc = make_float4(0.f, 0.f, 0.f, 0.f);
        for (int j = 0; j < c; j++) {
            int   s = nb[ebase + j];
            float w = wv[ebase + j];
            float4 xv = *(const float4*)(xg + (size_t)s * FD + lane * 4);
            acc.x += w * xv.x; acc.y += w * xv.y;
            acc.z += w * xv.z; acc.w += w * xv.w;
        }
        *(float4*)(outp + (size_t)gn * FD + lane * 4) = acc;
    } else {
        float2 acc = make_float2(0.f, 0.f);
        for (int j = 0; j < c; j++) {
            int   s = nb[ebase + j];
            float w = wv[ebase + j];
            float2 xv = *(const float2*)(xg + (size_t)s * FD + lane * 2);
            acc.x += w * xv.x; acc.y += w * xv.y;
        }
        *(float2*)(outp + (size_t)gn * FD + lane * 2) = acc;
    }
}

// ---------------- FMA2 GEMM: 128x128 block tile, 8x8/thread ---------------------
// Thread (ty,tx) owns rows ty*8..+7 and cols {tx*4..+3, 64+tx*4..+3} (conflict-free).
template<int KD, bool DUAL>
__global__ void __launch_bounds__(256)
gemm2_kernel(const float* __restrict__ A0, const float* __restrict__ A1,
             const float* __restrict__ W0, const float* __restrict__ W1,
             const float* __restrict__ b0, const float* __restrict__ b1,
             float* __restrict__ C, int M, int NC,
             float s0, float s1, float bs0, float bs1)
{
    __shared__ float As[16][132];
    __shared__ float Ws[16][132];
    const int tid = threadIdx.x;
    const int m0  = blockIdx.x * 128;
    const int jn  = blockIdx.y * 128;
    const int ty  = tid >> 4;
    const int tx  = tid & 15;

    u64 acc[8][4];
#pragma unroll
    for (int r = 0; r < 8; r++)
#pragma unroll
        for (int cidx = 0; cidx < 4; cidx++) acc[r][cidx] = 0ull;

    const int npass = DUAL ? 2 : 1;
    for (int pass = 0; pass < npass; pass++) {
        const float* A = pass ? A1 : A0;
        const float* W = pass ? W1 : W0;
        const float  s = pass ? s1 : s0;
        for (int kt = 0; kt < KD; kt += 16) {
            __syncthreads();
#pragma unroll
            for (int half = 0; half < 2; half++) {
                int r  = (tid >> 2) + half * 64;
                int k4 = (tid & 3) << 2;
                float4 v = *(const float4*)(A + (size_t)(m0 + r) * KD + kt + k4);
                As[k4 + 0][r] = v.x; As[k4 + 1][r] = v.y;
                As[k4 + 2][r] = v.z; As[k4 + 3][r] = v.w;
            }
#pragma unroll
            for (int half = 0; half < 2; half++) {
                int j  = (tid >> 2) + half * 64;
                int k4 = (tid & 3) << 2;
                float4 v = *(const float4*)(W + (size_t)(jn + j) * KD + kt + k4);
                Ws[k4 + 0][j] = v.x * s; Ws[k4 + 1][j] = v.y * s;
                Ws[k4 + 2][j] = v.z * s; Ws[k4 + 3][j] = v.w * s;
            }
            __syncthreads();
#pragma unroll
            for (int kk = 0; kk < 16; kk++) {
                float a[8];
                *(float4*)&a[0] = *(const float4*)&As[kk][ty * 8];
                *(float4*)&a[4] = *(const float4*)&As[kk][ty * 8 + 4];
                float4 wA = *(const float4*)&Ws[kk][tx * 4];
                float4 wB = *(const float4*)&Ws[kk][64 + tx * 4];
                u64 w01 = *(const u64*)&wA.x;
                u64 w23 = *(const u64*)&wA.z;
                u64 w45 = *(const u64*)&wB.x;
                u64 w67 = *(const u64*)&wB.z;
#pragma unroll
                for (int r = 0; r < 8; r++) {
                    u64 aa = pack2(a[r]);
                    acc[r][0] = fma2(aa, w01, acc[r][0]);
                    acc[r][1] = fma2(aa, w23, acc[r][1]);
                    acc[r][2] = fma2(aa, w45, acc[r][2]);
                    acc[r][3] = fma2(aa, w67, acc[r][3]);
                }
            }
        }
    }

    int j1 = jn + tx * 4;
    int j2 = jn + 64 + tx * 4;
    float biasA[4], biasB[4];
#pragma unroll
    for (int cidx = 0; cidx < 4; cidx++) {
        biasA[cidx] = bs0 * b0[j1 + cidx] + bs1 * b1[j1 + cidx];
        biasB[cidx] = bs0 * b0[j2 + cidx] + bs1 * b1[j2 + cidx];
    }
#pragma unroll
    for (int r = 0; r < 8; r++) {
        int m = m0 + ty * 8 + r;
        float2 p0 = *(float2*)&acc[r][0];
        float2 p1 = *(float2*)&acc[r][1];
        float2 p2 = *(float2*)&acc[r][2];
        float2 p3 = *(float2*)&acc[r][3];
        float4 o0 = make_float4(p0.x + biasA[0], p0.y + biasA[1], p1.x + biasA[2], p1.y + biasA[3]);
        float4 o1 = make_float4(p2.x + biasB[0], p2.y + biasB[1], p3.x + biasB[2], p3.y + biasB[3]);
        *(float4*)(C + (size_t)m * NC + j1) = o0;
        *(float4*)(C + (size_t)m * NC + j2) = o1;
    }
}

// ---------------- prep: Whh^T and Wp^T -------------------------------------------
__global__ void prep_kernel(const float* __restrict__ Whh, const float* __restrict__ Wp) {
    int i = blockIdx.x * blockDim.x + threadIdx.x;
    if (i < 512 * 128) {
        int j = i >> 7, k = i & 127;
        d_whhT[(size_t)k * 512 + j] = Whh[i];
    }
    if (i < 64 * 128) {
        int j = i >> 7, k = i & 127;
        d_wpT[k * 64 + j] = Wp[i];
    }
}

// ---------------- LSTM recurrence + fused projection ----------------------------
__device__ __forceinline__ float sigmoidf_(float x) { return 1.f / (1.f + __expf(-x)); }

__global__ void __launch_bounds__(256)
lstm_kernel(float* __restrict__ out, const float* __restrict__ bp)
{
    __shared__ float h_s[32][128];
    __shared__ float w_s[16][512];     // reused as Wp^T [128][64] in epilogue
    const int tid  = threadIdx.x;
    const int tc   = tid & 31;
    const int tr   = tid >> 5;
    const int row0 = blockIdx.x * 32 + tr * 4;

    float c[4][4];
#pragma unroll
    for (int a = 0; a < 4; a++)
#pragma unroll
        for (int b = 0; b < 4; b++) c[a][b] = 0.f;

    for (int t = 0; t < STEPS; t++) {
        u64 acc[4][4][2];   // [gate][row][colpair]
#pragma unroll
        for (int gate = 0; gate < 4; gate++)
#pragma unroll
            for (int ri = 0; ri < 4; ri++) {
                float4 v = *(const float4*)(d_gx +
                    ((size_t)(row0 + ri) * STEPS + t) * 512 + gate * 128 + tc * 4);
                acc[gate][ri][0] = *(const u64*)&v.x;
                acc[gate][ri][1] = *(const u64*)&v.z;
            }

        if (t > 0) {
            for (int kt = 0; kt < 8; kt++) {
                __syncthreads();
#pragma unroll
                for (int i = 0; i < 8; i++) {
                    int q  = tid + i * 256;
                    int kk = q >> 7;
                    int j4 = (q & 127) << 2;
                    *(float4*)&w_s[kk][j4] =
                        *(const float4*)(d_whhT + (size_t)(kt * 16 + kk) * 512 + j4);
                }
                __syncthreads();
#pragma unroll
                for (int kk = 0; kk < 16; kk++) {
                    u64 hp[4];
#pragma unroll
                    for (int ri = 0; ri < 4; ri++)
                        hp[ri] = pack2(h_s[tr * 4 + ri][kt * 16 + kk]);
#pragma unroll
                    for (int gate = 0; gate < 4; gate++) {
                        float4 w = *(const float4*)&w_s[kk][gate * 128 + tc * 4];
                        u64 w01 = *(const u64*)&w.x;
                        u64 w23 = *(const u64*)&w.z;
#pragma unroll
                        for (int ri = 0; ri < 4; ri++) {
                            acc[gate][ri][0] = fma2(hp[ri], w01, acc[gate][ri][0]);
                            acc[gate][ri][1] = fma2(hp[ri], w23, acc[gate][ri][1]);
                        }
                    }
                }
            }
            __syncthreads();
        }

#pragma unroll
        for (int ri = 0; ri < 4; ri++) {
            float2 i01 = *(float2*)&acc[0][ri][0], i23 = *(float2*)&acc[0][ri][1];
            float2 f01 = *(float2*)&acc[1][ri][0], f23 = *(float2*)&acc[1][ri][1];
            float2 g01 = *(float2*)&acc[2][ri][0], g23 = *(float2*)&acc[2][ri][1];
            float2 o01 = *(float2*)&acc[3][ri][0], o23 = *(float2*)&acc[3][ri][1];
            float ig[4] = {i01.x, i01.y, i23.x, i23.y};
            float fg[4] = {f01.x, f01.y, f23.x, f23.y};
            float gg[4] = {g01.x, g01.y, g23.x, g23.y};
            float og[4] = {o01.x, o01.y, o23.x, o23.y};
            float hn[4];
#pragma unroll
            for (int ci = 0; ci < 4; ci++) {
                float iv = sigmoidf_(ig[ci]);
                float fv = sigmoidf_(fg[ci]);
                float gv = tanhf(gg[ci]);
                float ov = sigmoidf_(og[ci]);
                float cn = fv * c[ri][ci] + iv * gv;
                c[ri][ci] = cn;
                hn[ci] = ov * tanhf(cn);
            }
            *(float4*)&h_s[tr * 4 + ri][tc * 4] = make_float4(hn[0], hn[1], hn[2], hn[3]);
        }
        __syncthreads();
    }

    // ---- fused projection: out[orow][0..63] = h_s[prow] @ Wp^T + bp ----
    float* wp = &w_s[0][0];   // reuse as [128][64]
#pragma unroll
    for (int i = 0; i < 8; i++) {
        int q = tid + i * 256;             // 2048 float4 chunks
        *(float4*)&wp[q * 4] = *(const float4*)(d_wpT + q * 4);
    }
    __syncthreads();

    const int prow = tid >> 3;             // 0..31
    const int cg   = tid & 7;              // cols cg*8..+7
    const int orow = blockIdx.x * 32 + prow;
    u64 pacc[4] = {0ull, 0ull, 0ull, 0ull};
#pragma unroll 8
    for (int k = 0; k < 128; k++) {
        u64 hv = pack2(h_s[prow][k]);
        float4 wa = *(const float4*)&wp[k * 64 + cg * 8];
        float4 wb = *(const float4*)&wp[k * 64 + cg * 8 + 4];
        pacc[0] = fma2(hv, *(const u64*)&wa.x, pacc[0]);
        pacc[1] = fma2(hv, *(const u64*)&wa.z, pacc[1]);
        pacc[2] = fma2(hv, *(const u64*)&wb.x, pacc[2]);
        pacc[3] = fma2(hv, *(const u64*)&wb.z, pacc[3]);
    }
    float4 bpa = *(const float4*)(bp + cg * 8);
    float4 bpb = *(const float4*)(bp + cg * 8 + 4);
    float2 q0 = *(float2*)&pacc[0];
    float2 q1 = *(float2*)&pacc[1];
    float2 q2 = *(float2*)&pacc[2];
    float2 q3 = *(float2*)&pacc[3];
    float4 o0 = make_float4(q0.x + bpa.x, q0.y + bpa.y, q1.x + bpa.z, q1.y + bpa.w);
    float4 o1 = make_float4(q2.x + bpb.x, q2.y + bpb.y, q3.x + bpb.z, q3.y + bpb.w);
    *(float4*)(out + (size_t)orow * 64 + cg * 8)     = o0;
    *(float4*)(out + (size_t)orow * 64 + cg * 8 + 4) = o1;
}

// ---------------- launch --------------------------------------------------------
extern "C" void kernel_launch(void* const* d_in, const int* in_sizes, int n_in,
                              void* d_out, int out_size)
{
    const float* x_seq = (const float*)d_in[0];
    const int*   ei    = (const int*)  d_in[1];
    const float* ew    = (const float*)d_in[2];
    const float* W0s   = (const float*)d_in[3];
    const float* b0s   = (const float*)d_in[4];
    const float* W0d   = (const float*)d_in[5];
    const float* b0d   = (const float*)d_in[6];
    const float* W1s   = (const float*)d_in[7];
    const float* b1s   = (const float*)d_in[8];
    const float* W1d   = (const float*)d_in[9];
    const float* b1d   = (const float*)d_in[10];
    const float* Wih   = (const float*)d_in[11];
    const float* Whh   = (const float*)d_in[12];
    const float* bih   = (const float*)d_in[13];
    const float* bhh   = (const float*)d_in[14];
    const float* Wp    = (const float*)d_in[15];
    const float* bp    = (const float*)d_in[16];
    float* out = (float*)d_out;

    float *aggf, *aggb, *h0, *h1, *gx;
    cudaGetSymbolAddress((void**)&aggf, d_aggf);
    cudaGetSymbolAddress((void**)&aggb, d_aggb);
    cudaGetSymbolAddress((void**)&h0,   d_h0);
    cudaGetSymbolAddress((void**)&h1,   d_h1);
    cudaGetSymbolAddress((void**)&gx,   d_gx);

    const int M = Gn * NN;   // 128000

    // ---- CSR build ----
    zero_kernel<<<(Gn * NN + 255) / 256, 256>>>();
    degcnt_kernel<<<(Gn * EE + 255) / 256, 256>>>(ei, ew);
    inv_kernel<<<(Gn * NN + 255) / 256, 256>>>();
    scan_kernel<<<dim3(Gn, 2), 1024>>>();
    scatter_kernel<<<(Gn * EE + 255) / 256, 256>>>(ei, ew);

    const int gblocks = (Gn * NN * 2 * 32 + 255) / 256;

    // ---- GCN layer 0 (F=64 -> H=128) ----
    gather_kernel<64><<<gblocks, 256>>>(x_seq);
    gemm2_kernel<64, true><<<dim3(M / 128, 1), 256>>>(
        aggf, aggb, W0s, W0d, b0s, b0d, h0, M, HD, 0.5f, 0.5f, 0.5f, 0.5f);

    // ---- GCN layer 1 (H=128 -> H=128) ----
    gather_kernel<128><<<gblocks, 256>>>(h0);
    gemm2_kernel<128, true><<<dim3(M / 128, 1), 256>>>(
        aggf, aggb, W1s, W1d, b1s, b1d, h1, M, HD, 0.5f, 0.5f, 0.5f, 0.5f);

    // ---- LSTM input GEMM: x@Wih.T + bih + bhh ----
    prep_kernel<<<256, 256>>>(Whh, Wp);
    gemm2_kernel<128, false><<<dim3(M / 128, 4), 256>>>(
        h1, nullptr, Wih, nullptr, bih, bhh, gx, M, 4 * HD, 1.f, 0.f, 1.f, 1.f);

    // ---- LSTM recurrence + fused projection ----
    lstm_kernel<<<BNR / 32, 256>>>(out, bp);
}